// round 13
// baseline (speedup 1.0000x reference)
#include <cuda_runtime.h>
#include <math.h>

#define BB 2
#define NN 18432
#define CC 1024
#define GRID_D 40
#define NUM_VOX 64000
#define KMAX 16          // max valid points per voxel (lambda~0.17)
#define ROWS_TOTAL (BB * NUM_VOX)
#define PERSIST_BLOCKS (148 * 8)

// Consolidated scratch: [cnt(ROWS)] [nval(ROWS)] [nwork(1)] [maxvox(BB)]
// Zero-initialized by one small memset. maxvox stores max(vid)+1 (0-init safe).
#define META_INTS (2 * ROWS_TOTAL + 1 + BB)
__device__ int g_meta[META_INTS];
__device__ int g_list[ROWS_TOTAL * KMAX];   // no reset needed (len = nval)
__device__ int g_work[ROWS_TOTAL];          // compacted non-empty row ids

#define G_CNT(v)   g_meta[(v)]
#define G_NVAL(v)  g_meta[ROWS_TOTAL + (v)]
#define G_NWORK    g_meta[2 * ROWS_TOTAL]
#define G_MAXV(b)  g_meta[2 * ROWS_TOTAL + 1 + (b)]

// ---------------------------------------------------------------------------
// K1: per-point voxel id / validity; voxel lists + compacted worklist
__global__ void k_points(const float* __restrict__ xyz) {
    int i = blockIdx.x * blockDim.x + threadIdx.x;
    if (i >= BB * NN) return;
    float x = xyz[3 * i + 0];
    float y = xyz[3 * i + 1];
    float z = xyz[3 * i + 2];
    bool valid = (x > -0.5f) && (x < 0.5f) &&
                 (y > -0.5f) && (y < 0.5f) &&
                 (z >  0.0f) && (z < 1.0f);
    if (!valid) { x = 0.f; y = 0.f; z = 0.f; }  // reference masks xyz to 0

    int ix = (int)floorf((x + 0.5f) * 40.0f);   // 1/0.025
    int iy = (int)floorf((y + 0.5f) * 40.0f);
    int iz = (int)floorf(z * 40.0f);
    ix = min(max(ix, 0), GRID_D - 1);
    iy = min(max(iy, 0), GRID_D - 1);
    iz = min(max(iz, 0), GRID_D - 1);
    int vid = ix + GRID_D * iy + GRID_D * GRID_D * iz;

    int b = i / NN;
    int slot = b * NUM_VOX + vid;
    atomicAdd(&G_CNT(slot), 1);                 // invalid points DO count
    atomicMax(&G_MAXV(b), vid + 1);             // stores max+1
    if (valid) {
        int j = atomicAdd(&G_NVAL(slot), 1);
        if (j < KMAX) g_list[slot * KMAX + j] = i;
        if (j == 0) {                           // first toucher compacts
            int w = atomicAdd(&G_NWORK, 1);
            g_work[w] = slot;
        }
    }
}

// ---------------------------------------------------------------------------
// K2: warp-per-row gather+mean+write, nv-specialized.
// ~95% of non-empty rows have exactly 1 valid point: that path is a scaled
// row copy with 8 float4 loads in flight and NO persistent accumulators,
// keeping registers low so occupancy stays high (the R11 failure mode).
__global__ __launch_bounds__(256) void k_gather(const float* __restrict__ feats,
                                                float* __restrict__ out,
                                                long pooled_elems,
                                                int write_offsets) {
    const int lane = threadIdx.x & 31;
    const int gw = (blockIdx.x * blockDim.x + threadIdx.x) >> 5;  // global warp
    const int nwarps = (gridDim.x * blockDim.x) >> 5;
    const int nwork = G_NWORK;

    for (int w = gw; w < nwork; w += nwarps) {
        int v = __ldg(&g_work[w]);
        int nv = min(__ldg(&G_NVAL(v)), KMAX);
        int cnt = __ldg(&G_CNT(v));             // >= nv >= 1
        float inv = 1.0f / (float)cnt;
        const int* lst = &g_list[v * KMAX];
        float4* dst = ((float4*)(out + (long)v * CC)) + lane;

        if (nv == 1) {
            // fast path: scaled copy, 8-deep MLP, transient registers only
            int p0 = __ldg(&lst[0]);
            const float4* src = ((const float4*)(feats + (long)p0 * CC)) + lane;
            float4 f0 = __ldcs(src + 0 * 32);
            float4 f1 = __ldcs(src + 1 * 32);
            float4 f2 = __ldcs(src + 2 * 32);
            float4 f3 = __ldcs(src + 3 * 32);
            float4 f4 = __ldcs(src + 4 * 32);
            float4 f5 = __ldcs(src + 5 * 32);
            float4 f6 = __ldcs(src + 6 * 32);
            float4 f7 = __ldcs(src + 7 * 32);
            f0.x *= inv; f0.y *= inv; f0.z *= inv; f0.w *= inv;
            f1.x *= inv; f1.y *= inv; f1.z *= inv; f1.w *= inv;
            f2.x *= inv; f2.y *= inv; f2.z *= inv; f2.w *= inv;
            f3.x *= inv; f3.y *= inv; f3.z *= inv; f3.w *= inv;
            f4.x *= inv; f4.y *= inv; f4.z *= inv; f4.w *= inv;
            f5.x *= inv; f5.y *= inv; f5.z *= inv; f5.w *= inv;
            f6.x *= inv; f6.y *= inv; f6.z *= inv; f6.w *= inv;
            f7.x *= inv; f7.y *= inv; f7.z *= inv; f7.w *= inv;
            __stcs(dst + 0 * 32, f0);
            __stcs(dst + 1 * 32, f1);
            __stcs(dst + 2 * 32, f2);
            __stcs(dst + 3 * 32, f3);
            __stcs(dst + 4 * 32, f4);
            __stcs(dst + 5 * 32, f5);
            __stcs(dst + 6 * 32, f6);
            __stcs(dst + 7 * 32, f7);
        } else {
            // rare path: chunk-outer / point-inner, one accumulator
#pragma unroll
            for (int k = 0; k < 8; k++) {
                int p0 = __ldg(&lst[0]);
                float4 acc = __ldcs(((const float4*)(feats + (long)p0 * CC))
                                    + lane + k * 32);
                for (int j = 1; j < nv; j++) {
                    int p = __ldg(&lst[j]);
                    float4 f = __ldcs(((const float4*)(feats + (long)p * CC))
                                      + lane + k * 32);
                    acc.x += f.x; acc.y += f.y; acc.z += f.z; acc.w += f.w;
                }
                acc.x *= inv; acc.y *= inv; acc.z *= inv; acc.w *= inv;
                __stcs(dst + k * 32, acc);
            }
        }
    }

    if (write_offsets && blockIdx.x == 0 && threadIdx.x == 0) {
        int acc = 0;
        for (int b = 0; b < BB; b++) {
            acc += G_MAXV(b);                   // already max(vid)+1
            out[pooled_elems + b] = (float)acc;
        }
    }
}

// ---------------------------------------------------------------------------
extern "C" void kernel_launch(void* const* d_in, const int* in_sizes, int n_in,
                              void* d_out, int out_size) {
    const float* feats;
    const float* xyz;
    if (in_sizes[0] == BB * NN * CC) {
        feats = (const float*)d_in[0];
        xyz   = (const float*)d_in[1];
    } else {
        feats = (const float*)d_in[1];
        xyz   = (const float*)d_in[0];
    }
    float* out = (float*)d_out;
    const long pooled_elems = (long)BB * NUM_VOX * CC;  // 131,072,000
    int write_offsets = ((long)out_size >= pooled_elems + BB) ? 1 : 0;

    // zero consolidated scratch (graph-capturable memset node)
    void* meta_ptr = nullptr;
    cudaGetSymbolAddress(&meta_ptr, g_meta);
    cudaMemsetAsync(meta_ptr, 0, sizeof(int) * META_INTS, 0);

    // per-point metadata + voxel lists + compaction
    k_points<<<(BB * NN + 255) / 256, 256>>>(xyz);

    // big output zero: driver memset alone runs at peak write BW
    cudaMemsetAsync(out, 0, (size_t)out_size * sizeof(float), 0);

    // warp-per-row gather/mean/write + offsets tail
    k_gather<<<PERSIST_BLOCKS, 256>>>(feats, out, pooled_elems, write_offsets);
}

// round 14
// speedup vs baseline: 1.0073x; 1.0073x over previous
#include <cuda_runtime.h>
#include <math.h>

#define BB 2
#define NN 18432
#define CC 1024
#define GRID_D 40
#define NUM_VOX 64000
#define KMAX 16          // max valid points per voxel (lambda~0.17)
#define ROWS_TOTAL (BB * NUM_VOX)
#define GROUP 8
#define NGROUP (ROWS_TOTAL / GROUP)   // 16000
#define PERSIST_BLOCKS (148 * 8)

// Consolidated scratch: [cnt(ROWS)] [nval(ROWS)] [maxvox(BB)]
#define META_INTS (2 * ROWS_TOTAL + BB)
__device__ int g_meta[META_INTS];
__device__ int g_list[ROWS_TOTAL * KMAX];   // no reset needed (len = nval)
__device__ int g_desc[ROWS_TOTAL];          // -1 empty | pidx copy | -2 slow

#define G_CNT(v)   g_meta[(v)]
#define G_NVAL(v)  g_meta[ROWS_TOTAL + (v)]
#define G_MAXV(b)  g_meta[2 * ROWS_TOTAL + (b)]

// ---------------------------------------------------------------------------
// K1: per-point voxel id / validity; voxel point lists
__global__ void k_points(const float* __restrict__ xyz) {
    int i = blockIdx.x * blockDim.x + threadIdx.x;
    if (i >= BB * NN) return;
    float x = xyz[3 * i + 0];
    float y = xyz[3 * i + 1];
    float z = xyz[3 * i + 2];
    bool valid = (x > -0.5f) && (x < 0.5f) &&
                 (y > -0.5f) && (y < 0.5f) &&
                 (z >  0.0f) && (z < 1.0f);
    if (!valid) { x = 0.f; y = 0.f; z = 0.f; }  // reference masks xyz to 0

    int ix = (int)floorf((x + 0.5f) * 40.0f);   // 1/0.025
    int iy = (int)floorf((y + 0.5f) * 40.0f);
    int iz = (int)floorf(z * 40.0f);
    ix = min(max(ix, 0), GRID_D - 1);
    iy = min(max(iy, 0), GRID_D - 1);
    iz = min(max(iz, 0), GRID_D - 1);
    int vid = ix + GRID_D * iy + GRID_D * GRID_D * iz;

    int b = i / NN;
    int slot = b * NUM_VOX + vid;
    atomicAdd(&G_CNT(slot), 1);                 // invalid points DO count
    atomicMax(&G_MAXV(b), vid + 1);             // stores max+1 (0-init safe)
    if (valid) {
        int j = atomicAdd(&G_NVAL(slot), 1);
        if (j < KMAX) g_list[slot * KMAX + j] = i;
    }
}

// ---------------------------------------------------------------------------
// K1b: dense per-row descriptor.
//  -1 : empty row (write zeros)                       ~84%
//  >=0: single valid point, cnt==1 -> raw row copy    ~15%
//  -2 : needs accumulate and/or scale (rare)
__global__ void k_desc() {
    int v = blockIdx.x * blockDim.x + threadIdx.x;
    if (v >= ROWS_TOTAL) return;
    int nv = G_NVAL(v);
    int d;
    if (nv == 0)                      d = -1;
    else if (nv == 1 && G_CNT(v) == 1) d = g_list[v * KMAX];
    else                              d = -2;
    g_desc[v] = d;
}

// ---------------------------------------------------------------------------
// K2: fused single-pass output writer. Each CTA iteration covers 8 consecutive
// rows (32KB contiguous). Thread t owns float4 column t of each row: 8
// independent stores per iteration, unrolled -> memset-grade ILP for the
// dominant all-empty case; copy rows add one ldcs; slow rows (~900) inline.
__global__ __launch_bounds__(256) void k_fused(const float* __restrict__ feats,
                                               float* __restrict__ out,
                                               long pooled_elems,
                                               int write_offsets) {
    const int t = threadIdx.x;
    const float4 zero = make_float4(0.f, 0.f, 0.f, 0.f);

    for (int g = blockIdx.x; g < NGROUP; g += gridDim.x) {
        const int4* d4 = (const int4*)&g_desc[g * GROUP];
        int4 da = __ldg(&d4[0]);
        int4 db = __ldg(&d4[1]);
        int dsc[GROUP] = {da.x, da.y, da.z, da.w, db.x, db.y, db.z, db.w};
        float4* base = ((float4*)(out + (long)g * GROUP * CC)) + t;

#pragma unroll
        for (int k = 0; k < GROUP; k++) {
            int d = dsc[k];                      // warp-uniform
            float4* dst = base + k * 256;
            if (d == -1) {
                __stcs(dst, zero);
            } else if (d >= 0) {
                __stcs(dst, __ldcs(((const float4*)(feats + (long)d * CC)) + t));
            } else {
                int v = g * GROUP + k;
                int nv = min(G_NVAL(v), KMAX);
                int cnt = G_CNT(v);
                float inv = 1.0f / (float)cnt;
                const int* lst = &g_list[v * KMAX];
                float4 acc = zero;
                for (int j = 0; j < nv; j++) {
                    int p = __ldg(&lst[j]);
                    float4 f = __ldcs(((const float4*)(feats + (long)p * CC)) + t);
                    acc.x += f.x; acc.y += f.y; acc.z += f.z; acc.w += f.w;
                }
                acc.x *= inv; acc.y *= inv; acc.z *= inv; acc.w *= inv;
                __stcs(dst, acc);
            }
        }
    }

    if (write_offsets && blockIdx.x == 0 && t == 0) {
        int acc = 0;
        for (int b = 0; b < BB; b++) {
            acc += G_MAXV(b);                    // already max(vid)+1
            out[pooled_elems + b] = (float)acc;
        }
    }
}

// ---------------------------------------------------------------------------
extern "C" void kernel_launch(void* const* d_in, const int* in_sizes, int n_in,
                              void* d_out, int out_size) {
    const float* feats;
    const float* xyz;
    if (in_sizes[0] == BB * NN * CC) {
        feats = (const float*)d_in[0];
        xyz   = (const float*)d_in[1];
    } else {
        feats = (const float*)d_in[1];
        xyz   = (const float*)d_in[0];
    }
    float* out = (float*)d_out;
    const long pooled_elems = (long)BB * NUM_VOX * CC;  // 131,072,000
    int write_offsets = ((long)out_size >= pooled_elems + BB) ? 1 : 0;

    // zero consolidated scratch (graph-capturable memset node)
    void* meta_ptr = nullptr;
    cudaGetSymbolAddress(&meta_ptr, g_meta);
    cudaMemsetAsync(meta_ptr, 0, sizeof(int) * META_INTS, 0);

    // per-point metadata + voxel lists
    k_points<<<(BB * NN + 255) / 256, 256>>>(xyz);

    // dense row descriptors
    k_desc<<<(ROWS_TOTAL + 255) / 256, 256>>>();

    // single fused pass: zeros + copies + means, one write of 524MB
    k_fused<<<PERSIST_BLOCKS, 256>>>(feats, out, pooled_elems, write_offsets);
}

// round 16
// speedup vs baseline: 1.2103x; 1.2014x over previous
#include <cuda_runtime.h>
#include <math.h>

#define BB 2
#define NN 18432
#define CC 1024
#define GRID_D 40
#define NUM_VOX 64000
#define KMAX 16          // max valid points per voxel (lambda~0.17)
#define ROWS_TOTAL (BB * NUM_VOX)
#define GROUP 8
#define NGROUP (ROWS_TOTAL / GROUP)   // 16000
#define PERSIST_BLOCKS (148 * 8)
#define INVALID_VID 820  // floor((0-(-0.5))/0.025) = 20 -> 20 + 40*20 + 0 = 820

// Consolidated scratch: [cnt(ROWS)] [nval(ROWS)] [maxvox(BB)]
#define META_INTS (2 * ROWS_TOTAL + BB)
__device__ int g_meta[META_INTS];
__device__ int g_list[ROWS_TOTAL * KMAX];   // no reset needed (len = nval)
__device__ int g_desc[ROWS_TOTAL];          // -1 empty | pidx copy | -2 slow

#define G_CNT(v)   g_meta[(v)]
#define G_NVAL(v)  g_meta[ROWS_TOTAL + (v)]
#define G_MAXV(b)  g_meta[2 * ROWS_TOTAL + (b)]

// ---------------------------------------------------------------------------
// K1: per-point voxel id / validity; voxel point lists.
// Contended atomics (maxvox: 2 addrs; invalid-count: vid 820 per batch) are
// block-aggregated in shared memory -> ~2 global atomics per block instead of
// ~256 (this was a 36.7us same-address serialization stall in R14).
__global__ void k_points(const float* __restrict__ xyz) {
    __shared__ int smax[BB];
    __shared__ int sinv[BB];
    const int t = threadIdx.x;
    if (t < BB) { smax[t] = 0; sinv[t] = 0; }
    __syncthreads();

    int i = blockIdx.x * blockDim.x + t;
    if (i < BB * NN) {
        float x = xyz[3 * i + 0];
        float y = xyz[3 * i + 1];
        float z = xyz[3 * i + 2];
        bool valid = (x > -0.5f) && (x < 0.5f) &&
                     (y > -0.5f) && (y < 0.5f) &&
                     (z >  0.0f) && (z < 1.0f);
        int b = i / NN;
        if (valid) {
            int ix = (int)floorf((x + 0.5f) * 40.0f);   // 1/0.025
            int iy = (int)floorf((y + 0.5f) * 40.0f);
            int iz = (int)floorf(z * 40.0f);
            ix = min(max(ix, 0), GRID_D - 1);
            iy = min(max(iy, 0), GRID_D - 1);
            iz = min(max(iz, 0), GRID_D - 1);
            int vid = ix + GRID_D * iy + GRID_D * GRID_D * iz;
            int slot = b * NUM_VOX + vid;
            atomicAdd(&G_CNT(slot), 1);          // spread addresses: fine
            int j = atomicAdd(&G_NVAL(slot), 1);
            if (j < KMAX) g_list[slot * KMAX + j] = i;
            atomicMax(&smax[b], vid + 1);        // shared, cheap
        } else {
            // masked to origin -> vid INVALID_VID; counts but contributes 0
            atomicAdd(&sinv[b], 1);
            atomicMax(&smax[b], INVALID_VID + 1);
        }
    }
    __syncthreads();

    if (t < BB) {
        if (smax[t] > 0) atomicMax(&G_MAXV(t), smax[t]);
        if (sinv[t] > 0) atomicAdd(&G_CNT(t * NUM_VOX + INVALID_VID), sinv[t]);
    }
}

// ---------------------------------------------------------------------------
// K1b: dense per-row descriptor.
//  -1 : empty row (write zeros)                       ~84%
//  >=0: single valid point, cnt==1 -> raw row copy    ~15%
//  -2 : needs accumulate and/or scale (rare)
__global__ void k_desc() {
    int v = blockIdx.x * blockDim.x + threadIdx.x;
    if (v >= ROWS_TOTAL) return;
    int nv = G_NVAL(v);
    int d;
    if (nv == 0)                       d = -1;
    else if (nv == 1 && G_CNT(v) == 1) d = g_list[v * KMAX];
    else                               d = -2;
    g_desc[v] = d;
}

// ---------------------------------------------------------------------------
// K2: fused single-pass output writer. Each CTA iteration covers 8 consecutive
// rows (32KB contiguous). Thread t owns float4 column t of each row: 8
// independent stores per iteration, unrolled -> memset-grade ILP for the
// dominant all-empty case; copy rows add one ldcs; slow rows (~900) inline.
__global__ __launch_bounds__(256) void k_fused(const float* __restrict__ feats,
                                               float* __restrict__ out,
                                               long pooled_elems,
                                               int write_offsets) {
    const int t = threadIdx.x;
    const float4 zero = make_float4(0.f, 0.f, 0.f, 0.f);

    for (int g = blockIdx.x; g < NGROUP; g += gridDim.x) {
        const int4* d4 = (const int4*)&g_desc[g * GROUP];
        int4 da = __ldg(&d4[0]);
        int4 db = __ldg(&d4[1]);
        int dsc[GROUP] = {da.x, da.y, da.z, da.w, db.x, db.y, db.z, db.w};
        float4* base = ((float4*)(out + (long)g * GROUP * CC)) + t;

#pragma unroll
        for (int k = 0; k < GROUP; k++) {
            int d = dsc[k];                      // warp-uniform
            float4* dst = base + k * 256;
            if (d == -1) {
                __stcs(dst, zero);
            } else if (d >= 0) {
                __stcs(dst, __ldcs(((const float4*)(feats + (long)d * CC)) + t));
            } else {
                int v = g * GROUP + k;
                int nv = min(G_NVAL(v), KMAX);
                int cnt = G_CNT(v);
                float inv = 1.0f / (float)cnt;
                const int* lst = &g_list[v * KMAX];
                float4 acc = zero;
                for (int j = 0; j < nv; j++) {
                    int p = __ldg(&lst[j]);
                    float4 f = __ldcs(((const float4*)(feats + (long)p * CC)) + t);
                    acc.x += f.x; acc.y += f.y; acc.z += f.z; acc.w += f.w;
                }
                acc.x *= inv; acc.y *= inv; acc.z *= inv; acc.w *= inv;
                __stcs(dst, acc);
            }
        }
    }

    if (write_offsets && blockIdx.x == 0 && t == 0) {
        int acc = 0;
        for (int b = 0; b < BB; b++) {
            acc += G_MAXV(b);                    // already max(vid)+1
            out[pooled_elems + b] = (float)acc;
        }
    }
}

// ---------------------------------------------------------------------------
extern "C" void kernel_launch(void* const* d_in, const int* in_sizes, int n_in,
                              void* d_out, int out_size) {
    const float* feats;
    const float* xyz;
    if (in_sizes[0] == BB * NN * CC) {
        feats = (const float*)d_in[0];
        xyz   = (const float*)d_in[1];
    } else {
        feats = (const float*)d_in[1];
        xyz   = (const float*)d_in[0];
    }
    float* out = (float*)d_out;
    const long pooled_elems = (long)BB * NUM_VOX * CC;  // 131,072,000
    int write_offsets = ((long)out_size >= pooled_elems + BB) ? 1 : 0;

    // zero consolidated scratch (graph-capturable memset node)
    void* meta_ptr = nullptr;
    cudaGetSymbolAddress(&meta_ptr, g_meta);
    cudaMemsetAsync(meta_ptr, 0, sizeof(int) * META_INTS, 0);

    // per-point metadata + voxel lists (block-aggregated hot atomics)
    k_points<<<(BB * NN + 255) / 256, 256>>>(xyz);

    // dense row descriptors
    k_desc<<<(ROWS_TOTAL + 255) / 256, 256>>>();

    // single fused pass: zeros + copies + means, one write of 524MB
    k_fused<<<PERSIST_BLOCKS, 256>>>(feats, out, pooled_elems, write_offsets);
}

// round 17
// speedup vs baseline: 1.2484x; 1.0316x over previous
#include <cuda_runtime.h>
#include <math.h>

#define BB 2
#define NN 18432
#define CC 1024
#define GRID_D 40
#define NUM_VOX 64000
#define KMAX 16          // max valid points per voxel (lambda~0.17)
#define ROWS_TOTAL (BB * NUM_VOX)
#define GROUP 8
#define NGROUP (ROWS_TOTAL / GROUP)   // 16000
#define PERSIST_BLOCKS (148 * 8)
#define INVALID_VID 820  // floor((0-(-0.5))/0.025)=20 -> 20 + 40*20 + 0 = 820

// Consolidated scratch: [cnt(ROWS)] [nval(ROWS)] [maxvox(BB)]
#define META_INTS (2 * ROWS_TOTAL + BB)
__device__ int g_meta[META_INTS];
__device__ int g_list[ROWS_TOTAL * KMAX];   // no reset needed (len = nval)

#define G_CNT(v)   g_meta[(v)]
#define G_NVAL(v)  g_meta[ROWS_TOTAL + (v)]
#define G_MAXV(b)  g_meta[2 * ROWS_TOTAL + (b)]

// ---------------------------------------------------------------------------
// K1: per-point voxel id / validity; voxel point lists.
// Hot same-address atomics (maxvox, invalid-count at vid 820) are
// block-aggregated in shared memory (R16 win: 36.7us -> 5.7us).
__global__ __launch_bounds__(128) void k_points(const float* __restrict__ xyz) {
    __shared__ int smax[BB];
    __shared__ int sinv[BB];
    const int t = threadIdx.x;
    if (t < BB) { smax[t] = 0; sinv[t] = 0; }
    __syncthreads();

    int i = blockIdx.x * blockDim.x + t;
    if (i < BB * NN) {
        float x = xyz[3 * i + 0];
        float y = xyz[3 * i + 1];
        float z = xyz[3 * i + 2];
        bool valid = (x > -0.5f) && (x < 0.5f) &&
                     (y > -0.5f) && (y < 0.5f) &&
                     (z >  0.0f) && (z < 1.0f);
        int b = i / NN;
        if (valid) {
            int ix = (int)floorf((x + 0.5f) * 40.0f);   // 1/0.025
            int iy = (int)floorf((y + 0.5f) * 40.0f);
            int iz = (int)floorf(z * 40.0f);
            ix = min(max(ix, 0), GRID_D - 1);
            iy = min(max(iy, 0), GRID_D - 1);
            iz = min(max(iz, 0), GRID_D - 1);
            int vid = ix + GRID_D * iy + GRID_D * GRID_D * iz;
            int slot = b * NUM_VOX + vid;
            atomicAdd(&G_CNT(slot), 1);          // spread addresses: fine
            int j = atomicAdd(&G_NVAL(slot), 1);
            if (j < KMAX) g_list[slot * KMAX + j] = i;
            atomicMax(&smax[b], vid + 1);        // shared, cheap
        } else {
            // masked to origin -> vid INVALID_VID; counts but contributes 0
            atomicAdd(&sinv[b], 1);
            atomicMax(&smax[b], INVALID_VID + 1);
        }
    }
    __syncthreads();

    if (t < BB) {
        if (smax[t] > 0) atomicMax(&G_MAXV(t), smax[t]);
        if (sinv[t] > 0) atomicAdd(&G_CNT(t * NUM_VOX + INVALID_VID), sinv[t]);
    }
}

// ---------------------------------------------------------------------------
// K2: fused single-pass output writer, desc computed inline from nval/cnt.
// Each CTA iteration covers 8 consecutive rows (32KB contiguous); thread t
// owns float4 column t of each row. Per group: 4 warp-uniform int4 meta loads
// (L2-resident), then 8 independent stores, unrolled. ~84% empty rows -> pure
// memset body; ~15% single-point rows -> 1 list lookup + row copy; slow rare.
__global__ __launch_bounds__(256) void k_fused(const float* __restrict__ feats,
                                               float* __restrict__ out,
                                               long pooled_elems,
                                               int write_offsets) {
    const int t = threadIdx.x;
    const float4 zero = make_float4(0.f, 0.f, 0.f, 0.f);

    for (int g = blockIdx.x; g < NGROUP; g += gridDim.x) {
        const int4* nv4 = (const int4*)&G_NVAL(g * GROUP);
        const int4* ct4 = (const int4*)&G_CNT(g * GROUP);
        int4 na = __ldg(&nv4[0]);
        int4 nb = __ldg(&nv4[1]);
        int4 ca = __ldg(&ct4[0]);
        int4 cb = __ldg(&ct4[1]);
        int nvs[GROUP] = {na.x, na.y, na.z, na.w, nb.x, nb.y, nb.z, nb.w};
        int cts[GROUP] = {ca.x, ca.y, ca.z, ca.w, cb.x, cb.y, cb.z, cb.w};
        float4* base = ((float4*)(out + (long)g * GROUP * CC)) + t;

#pragma unroll
        for (int k = 0; k < GROUP; k++) {
            int nv = nvs[k];                     // warp-uniform
            float4* dst = base + k * 256;
            if (nv == 0) {
                __stcs(dst, zero);
            } else if (nv == 1 && cts[k] == 1) {
                int p = __ldg(&g_list[(g * GROUP + k) * KMAX]);
                __stcs(dst, __ldcs(((const float4*)(feats + (long)p * CC)) + t));
            } else {
                int v = g * GROUP + k;
                int n = min(nv, KMAX);
                float inv = 1.0f / (float)cts[k];
                const int* lst = &g_list[v * KMAX];
                float4 acc = zero;
                for (int j = 0; j < n; j++) {
                    int p = __ldg(&lst[j]);
                    float4 f = __ldcs(((const float4*)(feats + (long)p * CC)) + t);
                    acc.x += f.x; acc.y += f.y; acc.z += f.z; acc.w += f.w;
                }
                acc.x *= inv; acc.y *= inv; acc.z *= inv; acc.w *= inv;
                __stcs(dst, acc);
            }
        }
    }

    if (write_offsets && blockIdx.x == 0 && t == 0) {
        int acc = 0;
        for (int b = 0; b < BB; b++) {
            acc += G_MAXV(b);                    // already max(vid)+1
            out[pooled_elems + b] = (float)acc;
        }
    }
}

// ---------------------------------------------------------------------------
extern "C" void kernel_launch(void* const* d_in, const int* in_sizes, int n_in,
                              void* d_out, int out_size) {
    const float* feats;
    const float* xyz;
    if (in_sizes[0] == BB * NN * CC) {
        feats = (const float*)d_in[0];
        xyz   = (const float*)d_in[1];
    } else {
        feats = (const float*)d_in[1];
        xyz   = (const float*)d_in[0];
    }
    float* out = (float*)d_out;
    const long pooled_elems = (long)BB * NUM_VOX * CC;  // 131,072,000
    int write_offsets = ((long)out_size >= pooled_elems + BB) ? 1 : 0;

    // zero consolidated scratch (graph-capturable memset node)
    void* meta_ptr = nullptr;
    cudaGetSymbolAddress(&meta_ptr, g_meta);
    cudaMemsetAsync(meta_ptr, 0, sizeof(int) * META_INTS, 0);

    // per-point metadata + voxel lists (block-aggregated hot atomics)
    k_points<<<(BB * NN + 127) / 128, 128>>>(xyz);

    // single fused pass: zeros + copies + means, one write of 524MB
    k_fused<<<PERSIST_BLOCKS, 256>>>(feats, out, pooled_elems, write_offsets);
}